// round 17
// baseline (speedup 1.0000x reference)
#include <cuda_runtime.h>
#include <cstdint>

#define NF 32
#define NPOLY 6545
#define BATCH 8192
#define NWARP 8
#define THREADS 256
#define NGROUP 8                      /* feature groups (blocks per row-tile) */
#define NCHUNKS (NGROUP * NWARP)      /* 64 balanced warp-chunks */
#define TILE_P 16                     /* W rows per smem tile */
#define NSTAGE 4                      /* cp.async ring depth */
#define WROW_BYTES (NF * 4)
#define XS_BYTES (32 * 33 * 4)                             /* 4224  */
#define WBUF_BYTES (NWARP * NSTAGE * TILE_P * WROW_BYTES)  /* 65536 */
#define SMEM_BYTES (XS_BYTES + WBUF_BYTES)                 /* 69760 */
#define NBLOCKS (256 * NGROUP)                             /* 2048 */

// scratch partials: [block][32 rows][32 cols]
__device__ float g_scratch[NBLOCKS * 1024];
// per-row-tile completion counters (wrap-reset by atomicInc, zero-init)
__device__ unsigned int g_cnt[256];

// ---------- PTX helpers ----------
__device__ __forceinline__ void cp16(uint32_t dst, const float* src) {
    unsigned long long g;
    asm volatile("cvta.to.global.u64 %0, %1;" : "=l"(g) : "l"(src));
    asm volatile("cp.async.cg.shared.global [%0], [%1], 16;" :: "r"(dst), "l"(g));
}
__device__ __forceinline__ void cp_commit() {
    asm volatile("cp.async.commit_group;" ::: "memory");
}
__device__ __forceinline__ void cp_wait0() {
    asm volatile("cp.async.wait_group 0;" ::: "memory");
}
__device__ __forceinline__ void cp_wait2() {
    asm volatile("cp.async.wait_group 2;" ::: "memory");
}
__device__ __forceinline__ unsigned long long pack2(float f) {
    unsigned long long r;
    asm("mov.b64 %0, {%1, %1};" : "=l"(r) : "f"(f));
    return r;
}
#define FMA2(a, w, f) asm("fma.rn.f32x2 %0, %1, %2, %0;" : "+l"(a) : "l"(w), "l"(f))

// Decode monomial index T -> walker state (f,a,b).
// f=-2: const+linear segment (b = position 0..32). f=-1: quadratic item a,
// offset b. f>=0: cubic item (f,a), offset b.
__device__ __forceinline__ void decode_T(int T, int& f, int& a, int& b) {
    if (T < 33) { f = -2; a = 0; b = T; return; }
    if (T < 561) {
        int r = T - 33;
        int aa = 0;
        while ((aa + 1) * (aa + 2) / 2 <= r) aa++;
        f = -1; a = aa; b = r - aa * (aa + 1) / 2; return;
    }
    int r = T - 561;
    int ff = 0;
    while ((ff + 1) * (ff + 2) * (ff + 3) / 6 <= r) ff++;
    r -= ff * (ff + 1) * (ff + 2) / 6;
    int aa = 0;
    while ((aa + 1) * (aa + 2) / 2 <= r) aa++;
    f = ff; a = aa; b = r - aa * (aa + 1) / 2;
}

// Stage one 16-row x 32-col fp32 W tile (2 KB) into smem (no commit).
__device__ __forceinline__ void load_tile(uint32_t dsts, const float* __restrict__ W,
                                          int row0, int lane) {
#pragma unroll
    for (int i = 0; i < 4; i++) {
        int e = i * 32 + lane;               // 16-byte unit index 0..127
        int r = row0 + (e >> 3);
        if (r > NPOLY - 1) r = NPOLY - 1;    // clamp (never consumed)
        cp16(dsts + (uint32_t)e * 16u, W + (size_t)r * NF + (e & 7) * 4);
    }
}

// One feature step. Thread covers 2 rows x 16 cols: V0 feeds row 2*rg,
// V1 feeds 2*rg+1. 4x LDS.128 of W (64B chunk per col-half) + 16 FMA2.
// Tile boundary: wait_group 2 (tile t's group complete; t+1, t+2 may be in
// flight), consume stage 0, prefetch tile t+3 into stage 3, ALWAYS commit
// (empty groups keep in-order group accounting valid at the tail), rotate.
#define STEP(V0, V1)                                                            \
    do {                                                                        \
        if ((tc & (TILE_P - 1)) == 0) {                                         \
            cp_wait2();                                                         \
            __syncwarp();                                                       \
            wcur = p0;                                                          \
            if (next_row < pend) {                                              \
                load_tile(a3, W, next_row, lane);                               \
                next_row += TILE_P;                                             \
            }                                                                   \
            cp_commit();                                                        \
            { char* tp = p0; p0 = p1; p1 = p2; p2 = p3; p3 = tp; }              \
            { uint32_t ta = a0; a0 = a1; a1 = a2; a2 = a3; a3 = ta; }           \
        }                                                                       \
        {                                                                       \
            const ulonglong2* wr = (const ulonglong2*)                          \
                (wcur + (tc & (TILE_P - 1)) * WROW_BYTES + cg * 64);            \
            unsigned long long f20 = pack2(V0);                                 \
            unsigned long long f21 = pack2(V1);                                 \
            ulonglong2 q0 = wr[0], q1 = wr[1], q2 = wr[2], q3 = wr[3];          \
            FMA2(acc[0], q0.x, f20); FMA2(acc[1], q0.y, f20);                   \
            FMA2(acc[2], q1.x, f20); FMA2(acc[3], q1.y, f20);                   \
            FMA2(acc[4], q2.x, f20); FMA2(acc[5], q2.y, f20);                   \
            FMA2(acc[6], q3.x, f20); FMA2(acc[7], q3.y, f20);                   \
            FMA2(acc[8],  q0.x, f21); FMA2(acc[9],  q0.y, f21);                 \
            FMA2(acc[10], q1.x, f21); FMA2(acc[11], q1.y, f21);                 \
            FMA2(acc[12], q2.x, f21); FMA2(acc[13], q2.y, f21);                 \
            FMA2(acc[14], q3.x, f21); FMA2(acc[15], q3.y, f21);                 \
            tc++;                                                               \
        }                                                                       \
    } while (0)

__global__ void __launch_bounds__(THREADS, 3)
taylor_fused(const float* __restrict__ x, const float* __restrict__ W,
             float* __restrict__ out) {
    extern __shared__ char smem[];
    __shared__ int s_last;
    float* xs = (float*)smem;             // [32][33] padded
    char* wbase = smem + XS_BYTES;        // 8 warps x 4 x 2KB ring buffers

    const int tid  = threadIdx.x;
    const int lane = tid & 31;
    const int w    = tid >> 5;
    const int rt   = blockIdx.x >> 3;     // row tile (0..255)
    const int gid  = blockIdx.x & (NGROUP - 1);
    const int row0 = rt * 32;

    // thread tile: 2 rows x 16 cols
    const int rg = lane & 15;             // row pair index (rows 2rg, 2rg+1)
    const int cg = lane >> 4;             // col half (0 or 1)

    // stage x tile (coalesced), padded stride 33
    for (int idx = tid; idx < 32 * 32; idx += THREADS) {
        int r = idx >> 5, c = idx & 31;
        xs[r * 33 + c] = x[(size_t)(row0 + r) * NF + c];
    }
    __syncthreads();

    const float* myx0 = xs + (2 * rg) * 33;
    const float* myx1 = myx0 + 33;

    // this warp's monomial range [pstart, pend), decoded in-warp
    const int chunk = gid * NWARP + w;
    const int pstart = (int)(((long long)NPOLY * chunk) / NCHUNKS);
    const int pend   = (int)(((long long)NPOLY * (chunk + 1)) / NCHUNKS);
    int f, a, b;
    decode_T(pstart, f, a, b);
    int rem = pend - pstart;

    // 4-stage ring buffers for this warp
    char* p0 = wbase + w * (NSTAGE * TILE_P * WROW_BYTES);
    char* p1 = p0 + TILE_P * WROW_BYTES;
    char* p2 = p1 + TILE_P * WROW_BYTES;
    char* p3 = p2 + TILE_P * WROW_BYTES;
    uint32_t a0 = (uint32_t)__cvta_generic_to_shared(p0);
    uint32_t a1 = a0 + TILE_P * WROW_BYTES;
    uint32_t a2 = a1 + TILE_P * WROW_BYTES;
    uint32_t a3 = a2 + TILE_P * WROW_BYTES;

    // preload 3 tiles (chunks are >= 102 rows, so all 3 exist; clamp guards OOB)
    load_tile(a0, W, pstart, lane);               cp_commit();
    load_tile(a1, W, pstart + TILE_P, lane);      cp_commit();
    load_tile(a2, W, pstart + 2 * TILE_P, lane);  cp_commit();
    int next_row = pstart + 3 * TILE_P;
    const char* wcur = p0;
    int tc = 0;

    unsigned long long acc[16];
#pragma unroll
    for (int i = 0; i < 16; i++) acc[i] = 0ULL;

    // walk the monomial items starting mid-stream at (f, a, b)
    while (rem > 0) {
        if (f == -2) {                       // const + linear (33 feats)
            int cnt = 33 - b; if (cnt > rem) cnt = rem;
            for (int i = 0; i < cnt; i++) {
                int bb = b + i;
                float v0 = (bb == 0) ? 1.0f : myx0[bb - 1];
                float v1 = (bb == 0) ? 1.0f : myx1[bb - 1];
                STEP(v0, v1);
            }
            rem -= cnt; b += cnt;
            if (b >= 33) { f = -1; a = 0; b = 0; }
        } else if (f == -1) {                // quadratic item a: x_a*x_b, b<=a
            int cnt = (a + 1) - b; if (cnt > rem) cnt = rem;
            float t0 = myx0[a], t1 = myx1[a];
            for (int i = 0; i < cnt; i++) STEP(t0 * myx0[b + i], t1 * myx1[b + i]);
            rem -= cnt; b += cnt;
            if (b > a) { b = 0; a++; if (a >= NF) { f = 0; a = 0; } }
        } else {                             // cubic item (f,a): x_f*x_a*x_b, b<=a
            int cnt = (a + 1) - b; if (cnt > rem) cnt = rem;
            float t0 = myx0[f] * myx0[a], t1 = myx1[f] * myx1[a];
            for (int i = 0; i < cnt; i++) STEP(t0 * myx0[b + i], t1 * myx1[b + i]);
            rem -= cnt; b += cnt;
            if (b > a) { b = 0; a++; if (a > f) { f++; a = 0; } }
        }
    }

    cp_wait0();          // drain all in-flight prefetch before smem overlay
    __syncthreads();

    // per-warp partials -> smem overlay, padded [8][32][33]
    float* red = (float*)smem;
    {
        float* rr0 = red + (w * 32 + 2 * rg) * 33 + 16 * cg;
        float* rr1 = rr0 + 33;
#pragma unroll
        for (int i = 0; i < 8; i++) {
            float lo, hi;
            asm("mov.b64 {%0, %1}, %2;" : "=f"(lo), "=f"(hi) : "l"(acc[i]));
            rr0[2 * i] = lo; rr0[2 * i + 1] = hi;
            asm("mov.b64 {%0, %1}, %2;" : "=f"(lo), "=f"(hi) : "l"(acc[8 + i]));
            rr1[2 * i] = lo; rr1[2 * i + 1] = hi;
        }
    }
    __syncthreads();

    // reduce 8 warps -> block partial in scratch (float4 per thread)
    const int idx4 = tid * 4;                // 0..1020
    {
        int r = idx4 >> 5, c = idx4 & 31;
        float4 s; s.x = 0.f; s.y = 0.f; s.z = 0.f; s.w = 0.f;
#pragma unroll
        for (int k = 0; k < NWARP; k++) {
            const float* rr = red + (k * 32 + r) * 33 + c;
            s.x += rr[0]; s.y += rr[1]; s.z += rr[2]; s.w += rr[3];
        }
        *(float4*)(g_scratch + (size_t)blockIdx.x * 1024 + idx4) = s;
    }

    // last block of this row-tile finishes: out = x + sum(groups)
    __threadfence();
    __syncthreads();
    if (tid == 0) {
        unsigned int old = atomicInc(&g_cnt[rt], NGROUP - 1);  // wraps 7 -> 0
        s_last = (old == NGROUP - 1);
    }
    __syncthreads();
    if (s_last) {
        size_t base = (size_t)rt * 1024 + idx4;   // x/out flat index
        float4 v = *(const float4*)(x + base);
#pragma unroll
        for (int g = 0; g < NGROUP; g++) {
            float4 t = __ldcg((const float4*)(g_scratch +
                              ((size_t)(rt * NGROUP + g) * 1024) + idx4));
            v.x += t.x; v.y += t.y; v.z += t.z; v.w += t.w;
        }
        *(float4*)(out + base) = v;
    }
}

extern "C" void kernel_launch(void* const* d_in, const int* in_sizes, int n_in,
                              void* d_out, int out_size) {
    const float* x = (const float*)d_in[0];
    const float* W = (const float*)d_in[1];
    if (n_in >= 2 && in_sizes[0] == NPOLY * NF && in_sizes[1] == BATCH * NF) {
        const float* t = x; x = W; W = t;
    }
    // 69.75 KB dynamic smem > 48 KB default: must raise the limit (host-side
    // attribute set; capture-legal — this was the R15 graph-capture failure).
    cudaFuncSetAttribute(taylor_fused,
                         cudaFuncAttributeMaxDynamicSharedMemorySize, SMEM_BYTES);
    taylor_fused<<<NBLOCKS, THREADS, SMEM_BYTES>>>(x, W, (float*)d_out);
}